// round 3
// baseline (speedup 1.0000x reference)
#include <cuda_runtime.h>
#include <cstdint>

#define THREADS 256
#define ROWS    256   // rows per block
#define NDIM    6
#define JLEV    8
#define CHAN    64

// ---------------------------------------------------------------------------
// One block handles ROWS consecutive rows:
//  phase 1: stage z chunk in SMEM (coalesced), compute packed big_index
//  phase 2: cooperative codebook-row gather -> coalesced 256B output rows
// ---------------------------------------------------------------------------
__global__ __launch_bounds__(THREADS)
void fsq_quantize_kernel(const float* __restrict__ z,
                         const float* __restrict__ perc,
                         const float* __restrict__ cb,
                         float* __restrict__ out_q,      // [B,64] or null
                         float* __restrict__ out_idx_f,  // [B] float tail or null
                         int*   __restrict__ out_idx_i,  // [B] int tail or null
                         int B)
{
    __shared__ float sz[ROWS * NDIM];     // 6 KB
    __shared__ float sp[JLEV * NDIM];     // 192 B
    __shared__ int   sidx[ROWS];          // 1 KB

    const int tid = threadIdx.x;
    const long long base = (long long)blockIdx.x * ROWS;
    const int nrows = (int)min((long long)ROWS, (long long)B - base);
    if (nrows <= 0) return;

    if (tid < JLEV * NDIM) sp[tid] = perc[tid];

    // coalesced streaming load of the z chunk
    const int total = nrows * NDIM;
    for (int e = tid; e < total; e += THREADS)
        sz[e] = __ldcs(&z[base * NDIM + e]);
    __syncthreads();

    if (tid < nrows) {
        int big = 0;
        #pragma unroll
        for (int i = 0; i < NDIM; i++) {
            const float v = sz[tid * NDIM + i];
            int idx = 0;
            // percentiles sorted per-dim: max{ j : v >= p[j] } == count over j>=1
            #pragma unroll
            for (int j = 1; j < JLEV; j++)
                idx += (v >= sp[j * NDIM + i]) ? 1 : 0;
            big |= idx << (3 * i);   // basis = 8^i
        }
        sidx[tid] = big;
        if (out_idx_f) out_idx_f[base + tid] = (float)big;
        if (out_idx_i) out_idx_i[base + tid] = big;
    }
    __syncthreads();

    if (out_q) {
        // 16 lanes x float4 per row: codebook row = 256B (2 L2 lines), output
        // rows contiguous and fully coalesced. Streaming store keeps the
        // 512MB output flow from evicting the L2-resident codebook.
        const int totalv = nrows * (CHAN / 4);
        for (int e = tid; e < totalv; e += THREADS) {
            const int r = e >> 4;
            const int c = e & 15;
            const float4* src =
                (const float4*)(cb + (long long)sidx[r] * CHAN) + c;
            const float4 v = __ldg(src);
            float4* dst = (float4*)(out_q + (base + r) * (long long)CHAN) + c;
            __stcs(dst, v);
        }
    }
}

extern "C" void kernel_launch(void* const* d_in, const int* in_sizes, int n_in,
                              void* d_out, int out_size)
{
    const float* z    = (const float*)d_in[0];   // [B,6]
    const float* perc = (const float*)d_in[1];   // [8,6]
    const float* cb   = (const float*)d_in[2];   // [262144,64]
    const int B = in_sizes[0] / NDIM;

    const long long nq = (long long)B * CHAN;

    float* out_q     = nullptr;
    float* out_idx_f = nullptr;
    int*   out_idx_i = nullptr;

    if ((long long)out_size == nq) {
        // quantized only
        out_q = (float*)d_out;
    } else if ((long long)out_size == nq + B) {
        // quantized followed by big_index; assume float32-promoted concat
        out_q = (float*)d_out;
        out_idx_f = (float*)d_out + nq;
    } else if (out_size == B) {
        // big_index only -> int32
        out_idx_i = (int*)d_out;
    } else {
        // fallback: treat as quantized region of whatever fits
        out_q = (float*)d_out;
    }

    const int blocks = (B + ROWS - 1) / ROWS;
    fsq_quantize_kernel<<<blocks, THREADS>>>(z, perc, cb, out_q, out_idx_f,
                                             out_idx_i, B);
}

// round 5
// speedup vs baseline: 1.0147x; 1.0147x over previous
#include <cuda_runtime.h>
#include <cstdint>

#define THREADS 256
#define ROWS    256   // rows per block
#define NDIM    6
#define JLEV    8
#define CHAN    64

// ---------------------------------------------------------------------------
// One block handles ROWS consecutive rows:
//  phase 1: stage z chunk in SMEM (float4-coalesced), compute packed big_index
//  phase 2: cooperative codebook gather, MLP-4 pipelined, 256B coalesced rows
// ---------------------------------------------------------------------------
__global__ __launch_bounds__(THREADS)
void fsq_quantize_kernel(const float* __restrict__ z,
                         const float* __restrict__ perc,
                         const float* __restrict__ cb,
                         float* __restrict__ out_q,      // [B,64]
                         float* __restrict__ out_idx_f,  // [B] float tail
                         int B)
{
    __shared__ float sz[ROWS * NDIM];     // 6 KB
    __shared__ float sp[JLEV * NDIM];     // 192 B
    __shared__ int   sidx[ROWS];          // 1 KB

    const int tid = threadIdx.x;
    const long long base = (long long)blockIdx.x * ROWS;
    const bool full = (base + ROWS) <= (long long)B;
    const int nrows = full ? ROWS : (int)((long long)B - base);
    if (nrows <= 0) return;

    if (tid < JLEV * NDIM) sp[tid] = perc[tid];

    if (full) {
        // 1536 floats = 384 float4, block offset 6144B -> 16B aligned
        float4* szv = (float4*)sz;
        const float4* zv = (const float4*)(z + base * NDIM);
        szv[tid] = __ldcs(&zv[tid]);                       // 256
        if (tid < 128) szv[256 + tid] = __ldcs(&zv[256 + tid]);  // +128 = 384
    } else {
        const int total = nrows * NDIM;
        for (int e = tid; e < total; e += THREADS)
            sz[e] = __ldcs(&z[base * NDIM + e]);
    }
    __syncthreads();

    if (tid < nrows) {
        int big = 0;
        #pragma unroll
        for (int i = 0; i < NDIM; i++) {
            const float v = sz[tid * NDIM + i];
            int idx = 0;
            // percentiles sorted per-dim: max{ j : v >= p[j] } == count over j>=1
            #pragma unroll
            for (int j = 1; j < JLEV; j++)
                idx += (v >= sp[j * NDIM + i]) ? 1 : 0;
            big |= idx << (3 * i);   // basis = 8^i
        }
        sidx[tid] = big;
        if (out_idx_f) out_idx_f[base + tid] = (float)big;
    }
    __syncthreads();

    if (!out_q) return;

    if (full) {
        // 16 lanes x float4 per row. 4096 float4 per block; each thread does
        // 16 vectors in 4 batches of 4 independent loads (explicit MLP=4).
        // __ldcg: codebook never fits L1 -> skip L1 allocation entirely.
        float4* dstb = (float4*)(out_q + base * (long long)CHAN);
        #pragma unroll
        for (int u0 = 0; u0 < 16; u0 += 4) {
            const float4* s[4];
            #pragma unroll
            for (int k = 0; k < 4; k++) {
                const int e = (u0 + k) * THREADS + tid;
                s[k] = (const float4*)(cb + (long long)sidx[e >> 4] * CHAN)
                       + (e & 15);
            }
            float4 v0 = __ldcg(s[0]);
            float4 v1 = __ldcg(s[1]);
            float4 v2 = __ldcg(s[2]);
            float4 v3 = __ldcg(s[3]);
            __stcs(&dstb[(u0 + 0) * THREADS + tid], v0);
            __stcs(&dstb[(u0 + 1) * THREADS + tid], v1);
            __stcs(&dstb[(u0 + 2) * THREADS + tid], v2);
            __stcs(&dstb[(u0 + 3) * THREADS + tid], v3);
        }
    } else {
        const int totalv = nrows * (CHAN / 4);
        for (int e = tid; e < totalv; e += THREADS) {
            const int r = e >> 4;
            const int c = e & 15;
            const float4 v =
                __ldcg((const float4*)(cb + (long long)sidx[r] * CHAN) + c);
            __stcs((float4*)(out_q + (base + r) * (long long)CHAN) + c, v);
        }
    }
}

extern "C" void kernel_launch(void* const* d_in, const int* in_sizes, int n_in,
                              void* d_out, int out_size)
{
    const float* z    = (const float*)d_in[0];   // [B,6]
    const float* perc = (const float*)d_in[1];   // [8,6]
    const float* cb   = (const float*)d_in[2];   // [262144,64]
    const int B = in_sizes[0] / NDIM;

    const long long nq = (long long)B * CHAN;

    float* out_q     = (float*)d_out;
    float* out_idx_f = nullptr;
    if ((long long)out_size == nq + B)
        out_idx_f = (float*)d_out + nq;   // confirmed layout: [B*64 | B]

    const int blocks = (B + ROWS - 1) / ROWS;
    fsq_quantize_kernel<<<blocks, THREADS>>>(z, perc, cb, out_q, out_idx_f, B);
}